// round 7
// baseline (speedup 1.0000x reference)
#include <cuda_runtime.h>
#include <cuda_bf16.h>
#include <stdint.h>

// BiLSTM B=128,S=1024,D=128,H=256 — bf16 3-split HMMA + cluster DSMEM exchange.
// Grid 128 = 16 clusters x 8 CTAs. Cluster = (dir, btile) exchange group;
// rank rs = rowslice (M=128 rows = 4 gates x 32 h). Each CTA: N=16 batches.
// h exchanged via st.shared::cluster into all peers' B-region (bf16 hi/lo,
// ldsm-ready) with full/empty mbarrier handshake. No global state.

#define S_LEN 1024
#define NTHR  256

#define A_HI_OFF 0          // 8mt x 24kt x 512B
#define A_LO_OFF 98304
#define B_HI_OFF 196608     // [384][16] bf16, 32B rows
#define B_LO_OFF 208896
#define Z_OFF    221184     // float z[128][16]
#define SG_OFF   229376     // staging: hi[32][16]bf16 (1KB) + lo (1KB)
#define CTRL_OFF 231424     // +0 full mbar, +8 empty mbar
#define SMEM_BYTES 231488

__device__ __forceinline__ uint32_t smem_u32(const void* p) {
    uint32_t a;
    asm("{ .reg .u64 t; cvta.to.shared.u64 t, %1; cvt.u32.u64 %0, t; }"
        : "=r"(a) : "l"(p));
    return a;
}
__device__ __forceinline__ uint32_t mapa_u32(uint32_t a, uint32_t rank) {
    uint32_t r;
    asm("mapa.shared::cluster.u32 %0, %1, %2;" : "=r"(r) : "r"(a), "r"(rank));
    return r;
}
__device__ __forceinline__ void st_cluster_u64(uint32_t a, uint64_t v) {
    asm volatile("st.shared::cluster.u64 [%0], %1;" :: "r"(a), "l"(v) : "memory");
}
__device__ __forceinline__ void mbar_init(uint32_t m, uint32_t cnt) {
    asm volatile("mbarrier.init.shared.b64 [%0], %1;" :: "r"(m), "r"(cnt) : "memory");
}
__device__ __forceinline__ void mbar_arrive_cluster(uint32_t a) {
    asm volatile("mbarrier.arrive.release.cluster.shared::cluster.b64 _, [%0];"
                 :: "r"(a) : "memory");
}
__device__ __forceinline__ void mbar_wait(uint32_t m, uint32_t ph) {
    asm volatile(
        "{\n\t.reg .pred P;\n\t"
        "WL%=:\n\t"
        "mbarrier.try_wait.parity.acquire.cluster.shared::cta.b64 P, [%0], %1;\n\t"
        "@P bra.uni WD%=;\n\t"
        "bra.uni WL%=;\n\t"
        "WD%=:\n\t}"
        :: "r"(m), "r"(ph) : "memory");
}
__device__ __forceinline__ void fence_cluster() {
    asm volatile("fence.acq_rel.cluster;" ::: "memory");
}
__device__ __forceinline__ void cluster_sync() {
    asm volatile("barrier.cluster.arrive.aligned;" ::: "memory");
    asm volatile("barrier.cluster.wait.aligned;" ::: "memory");
}
__device__ __forceinline__ void ldsm4(uint32_t* r, uint32_t a) {
    asm volatile("ldmatrix.sync.aligned.m8n8.x4.shared.b16 {%0,%1,%2,%3}, [%4];"
                 : "=r"(r[0]), "=r"(r[1]), "=r"(r[2]), "=r"(r[3]) : "r"(a));
}
__device__ __forceinline__ void ldsm4t(uint32_t* r, uint32_t a) {
    asm volatile("ldmatrix.sync.aligned.m8n8.x4.trans.shared.b16 {%0,%1,%2,%3}, [%4];"
                 : "=r"(r[0]), "=r"(r[1]), "=r"(r[2]), "=r"(r[3]) : "r"(a));
}
__device__ __forceinline__ void mma16816(float* d, const uint32_t* a, const uint32_t* b) {
    asm volatile(
        "mma.sync.aligned.m16n8k16.row.col.f32.bf16.bf16.f32 "
        "{%0,%1,%2,%3}, {%4,%5,%6,%7}, {%8,%9}, {%0,%1,%2,%3};"
        : "+f"(d[0]), "+f"(d[1]), "+f"(d[2]), "+f"(d[3])
        : "r"(a[0]), "r"(a[1]), "r"(a[2]), "r"(a[3]), "r"(b[0]), "r"(b[1]));
}

__device__ __forceinline__ uint2 split_pack4(float4 v, uint2& lo_out) {
    __nv_bfloat16 h0 = __float2bfloat16_rn(v.x), h1 = __float2bfloat16_rn(v.y);
    __nv_bfloat16 h2 = __float2bfloat16_rn(v.z), h3 = __float2bfloat16_rn(v.w);
    __nv_bfloat16 l0 = __float2bfloat16_rn(v.x - __bfloat162float(h0));
    __nv_bfloat16 l1 = __float2bfloat16_rn(v.y - __bfloat162float(h1));
    __nv_bfloat16 l2 = __float2bfloat16_rn(v.z - __bfloat162float(h2));
    __nv_bfloat16 l3 = __float2bfloat16_rn(v.w - __bfloat162float(h3));
    uint2 hi;
    hi.x = ((uint32_t)__bfloat16_as_ushort(h1) << 16) | __bfloat16_as_ushort(h0);
    hi.y = ((uint32_t)__bfloat16_as_ushort(h3) << 16) | __bfloat16_as_ushort(h2);
    lo_out.x = ((uint32_t)__bfloat16_as_ushort(l1) << 16) | __bfloat16_as_ushort(l0);
    lo_out.y = ((uint32_t)__bfloat16_as_ushort(l3) << 16) | __bfloat16_as_ushort(l2);
    return hi;
}
__device__ __forceinline__ float sigmoidf_fast(float x) {
    return 1.0f / (1.0f + __expf(-x));
}
__device__ __forceinline__ float tanhf_fast(float x) {
    return 1.0f - 2.0f / (1.0f + __expf(2.0f * x));
}

__global__ void __launch_bounds__(NTHR, 1) __cluster_dims__(8, 1, 1)
bilstm_mma_kernel(const float* __restrict__ x,
                  const float* __restrict__ Wf, const float* __restrict__ bf,
                  const float* __restrict__ Wb, const float* __restrict__ bb,
                  float* __restrict__ out)
{
    extern __shared__ char smem[];
    const uint32_t sb = smem_u32(smem);
    const int tid  = threadIdx.x;
    const int wid  = tid >> 5;
    const int lane = tid & 31;

    const int dir = blockIdx.x >> 6;
    const int btl = (blockIdx.x >> 3) & 7;
    const int rs  = blockIdx.x & 7;          // cluster rank = rowslice
    const int b_base = btl * 16;

    const float* W   = dir ? Wb : Wf;        // (4,256,384)
    const float* bia = dir ? bb : bf;
    float* z_s = (float*)(smem + Z_OFF);

    const uint32_t fullbar  = sb + CTRL_OFF;
    const uint32_t emptybar = sb + CTRL_OFF + 8;

    if (tid == 0) { mbar_init(fullbar, 8); mbar_init(emptybar, 8); }

    // zero h-region rows 128..383 of both B buffers
    for (int i = tid; i < 512; i += NTHR) {
        ((uint4*)(smem + B_HI_OFF + 4096))[i] = make_uint4(0, 0, 0, 0);
        ((uint4*)(smem + B_LO_OFF + 4096))[i] = make_uint4(0, 0, 0, 0);
    }

    // ---- A: weights -> bf16 hi/lo ldmatrix tiles ----
    for (int idx = tid; idx < 128 * 96; idx += NTHR) {
        int r = idx / 96, j = idx % 96, k0 = j * 4;
        int wr = (r >> 5) * 256 + rs * 32 + (r & 31);
        float4 v = *(const float4*)(W + (size_t)wr * 384 + k0);
        uint2 lo, hi = split_pack4(v, lo);
        uint32_t byte = (uint32_t)(((r >> 4) * 24 + (k0 >> 4)) * 512
                       + (((k0 >> 3) & 1) * 2 + ((r >> 3) & 1)) * 128
                       + (r & 7) * 16 + (k0 & 7) * 2);
        *(uint2*)(smem + A_HI_OFF + byte) = hi;
        *(uint2*)(smem + A_LO_OFF + byte) = lo;
    }

    const int r1 = wid * 16 + (lane >> 2);
    const int r2 = r1 + 8;
    const float bv1 = bia[(r1 >> 5) * 256 + rs * 32 + (r1 & 31)];
    const float bv2 = bia[(r2 >> 5) * 256 + rs * 32 + (r2 & 31)];

    // x(0) fill directly into B rows 0..127
    {
        const int t0 = dir ? (S_LEN - 1) : 0;
        for (int i = tid; i < 512; i += NTHR) {
            int k = i >> 2, j = i & 3;
            float4 v = __ldg((const float4*)(x + (size_t)k * (S_LEN * 128)
                                               + (size_t)t0 * 128 + b_base + j * 4));
            uint2 lo, hi = split_pack4(v, lo);
            *(uint2*)(smem + B_HI_OFF + k * 32 + j * 8) = hi;
            *(uint2*)(smem + B_LO_OFF + k * 32 + j * 8) = lo;
        }
    }

    // precompute remote addrs: publish chunk + barriers
    const int pbuf = tid >> 7;               // 0=hi, 1=lo
    const int pkr  = (tid >> 2) & 31;        // k row 0..31
    const int pch  = tid & 3;                // 8B chunk
    const uint32_t sg_src = sb + SG_OFF + pbuf * 1024 + pkr * 32 + pch * 8;
    const uint32_t dst_local = sb + (pbuf ? B_LO_OFF : B_HI_OFF)
                             + (uint32_t)(128 + rs * 32 + pkr) * 32 + pch * 8;
    uint32_t dstp[8], fbp[8], ebp[8];
#pragma unroll
    for (int p = 0; p < 8; ++p) {
        dstp[p] = mapa_u32(dst_local, (uint32_t)p);
        fbp[p]  = mapa_u32(fullbar,  (uint32_t)p);
        ebp[p]  = mapa_u32(emptybar, (uint32_t)p);
    }

    __syncthreads();
    cluster_sync();   // barriers initialized + zeros visible cluster-wide

    // ldmatrix base addrs
    const uint32_t aHi0 = sb + A_HI_OFF + (uint32_t)(wid * 24 * 512)
                        + ((lane >> 3) * 128) + ((lane & 7) * 16);
    const int sub = lane >> 3;
    const int kk  = (lane & 7) + (sub & 1) * 8;
    const int nb  = sub >> 1;
    const uint32_t bHi0 = sb + B_HI_OFF + (uint32_t)(kk * 32 + nb * 16);

    // gate cells
    const int cb  = tid & 15;
    const int hh0 = (tid >> 4) << 1;
    float c0 = 0.0f, c1 = 0.0f;

    for (int s = 0; s < S_LEN; ++s) {
        const int t = dir ? (S_LEN - 1 - s) : s;

        float a0e[4] = {0,0,0,0}, a0o[4] = {0,0,0,0};
        float a1e[4] = {0,0,0,0}, a1o[4] = {0,0,0,0};
        uint32_t aH = aHi0, bH = bHi0;

        // ---- x-part GEMM: kt 0..7 ----
#pragma unroll
        for (int kt = 0; kt < 8; ++kt) {
            uint32_t ah[4], al[4], bh[4], bl[4];
            ldsm4 (ah, aH);
            ldsm4 (al, aH + 98304u);
            ldsm4t(bh, bH);
            ldsm4t(bl, bH + 12288u);
            float* A0 = (kt & 1) ? a0o : a0e;
            float* A1 = (kt & 1) ? a1o : a1e;
            mma16816(A0, ah, bh);  mma16816(A1, ah, bh + 2);
            mma16816(A0, ah, bl);  mma16816(A1, ah, bl + 2);
            mma16816(A0, al, bh);  mma16816(A1, al, bh + 2);
            aH += 512u; bH += 512u;
        }

        // ---- wait for h(s-1) (DSMEM-delivered), then h-part GEMM ----
        if (s > 0) mbar_wait(fullbar, (uint32_t)((s - 1) & 1));
#pragma unroll
        for (int kt = 0; kt < 16; ++kt) {
            uint32_t ah[4], al[4], bh[4], bl[4];
            ldsm4 (ah, aH);
            ldsm4 (al, aH + 98304u);
            ldsm4t(bh, bH);
            ldsm4t(bl, bH + 12288u);
            float* A0 = (kt & 1) ? a0o : a0e;
            float* A1 = (kt & 1) ? a1o : a1e;
            mma16816(A0, ah, bh);  mma16816(A1, ah, bh + 2);
            mma16816(A0, ah, bl);  mma16816(A1, ah, bl + 2);
            mma16816(A0, al, bh);  mma16816(A1, al, bh + 2);
            aH += 512u; bH += 512u;
        }

        // ---- stage z (+bias) ----
        const int n0 = (lane & 3) * 2;
        *(float2*)(z_s + r1 * 16 + n0)     = make_float2(a0e[0] + a0o[0] + bv1, a0e[1] + a0o[1] + bv1);
        *(float2*)(z_s + r2 * 16 + n0)     = make_float2(a0e[2] + a0o[2] + bv2, a0e[3] + a0o[3] + bv2);
        *(float2*)(z_s + r1 * 16 + n0 + 8) = make_float2(a1e[0] + a1o[0] + bv1, a1e[1] + a1o[1] + bv1);
        *(float2*)(z_s + r2 * 16 + n0 + 8) = make_float2(a1e[2] + a1o[2] + bv2, a1e[3] + a1o[3] + bv2);
        __syncthreads();                     // z visible; all h reads done
        if (tid == 0) {                      // B h-region free for overwrite
#pragma unroll
            for (int p = 0; p < 8; ++p) mbar_arrive_cluster(ebp[p]);
        }

        // ---- gates ----
        float zf0 = z_s[(0  + hh0) * 16 + cb], zf1 = z_s[(1  + hh0) * 16 + cb];
        float zi0 = z_s[(32 + hh0) * 16 + cb], zi1 = z_s[(33 + hh0) * 16 + cb];
        float zc0 = z_s[(64 + hh0) * 16 + cb], zc1 = z_s[(65 + hh0) * 16 + cb];
        float zo0 = z_s[(96 + hh0) * 16 + cb], zo1 = z_s[(97 + hh0) * 16 + cb];

        // prefetch x(s+1) into registers (hide LDG behind gates/publish)
        float4 rx0, rx1;
        if (s + 1 < S_LEN) {
            const int tn = dir ? (S_LEN - 2 - s) : (s + 1);
            int k0 = tid >> 2, j0 = tid & 3;
            rx0 = __ldg((const float4*)(x + (size_t)k0 * (S_LEN * 128)
                                          + (size_t)tn * 128 + b_base + j0 * 4));
            int i1 = tid + 256;
            int k1 = i1 >> 2, j1 = i1 & 3;
            rx1 = __ldg((const float4*)(x + (size_t)k1 * (S_LEN * 128)
                                          + (size_t)tn * 128 + b_base + j1 * 4));
        }

        c0 = sigmoidf_fast(zf0) * c0 + sigmoidf_fast(zi0) * tanhf_fast(zc0);
        c1 = sigmoidf_fast(zf1) * c1 + sigmoidf_fast(zi1) * tanhf_fast(zc1);
        float hv0 = sigmoidf_fast(zo0) * tanhf_fast(c0);
        float hv1 = sigmoidf_fast(zo1) * tanhf_fast(c1);

        // stage h -> sg (bf16 hi/lo)
        {
            __nv_bfloat16 h0 = __float2bfloat16_rn(hv0);
            __nv_bfloat16 h1 = __float2bfloat16_rn(hv1);
            __nv_bfloat16 l0 = __float2bfloat16_rn(hv0 - __bfloat162float(h0));
            __nv_bfloat16 l1 = __float2bfloat16_rn(hv1 - __bfloat162float(h1));
            *(unsigned short*)(smem + SG_OFF + hh0 * 32 + cb * 2)          = __bfloat16_as_ushort(h0);
            *(unsigned short*)(smem + SG_OFF + (hh0 + 1) * 32 + cb * 2)    = __bfloat16_as_ushort(h1);
            *(unsigned short*)(smem + SG_OFF + 1024 + hh0 * 32 + cb * 2)       = __bfloat16_as_ushort(l0);
            *(unsigned short*)(smem + SG_OFF + 1024 + (hh0 + 1) * 32 + cb * 2) = __bfloat16_as_ushort(l1);
        }
        __syncthreads();                     // sg complete

        if (s + 1 < S_LEN) {
            // ---- publish h(s) to all 8 CTAs' B h-region ----
            mbar_wait(emptybar, (uint32_t)(s & 1));   // all peers done reading
            uint64_t v = *(const uint64_t*)(smem + (sg_src - sb));
#pragma unroll
            for (int p = 0; p < 8; ++p) st_cluster_u64(dstp[p], v);
            fence_cluster();
            __syncthreads();
            if (tid == 0) {
#pragma unroll
                for (int p = 0; p < 8; ++p) mbar_arrive_cluster(fbp[p]);
            }
            // ---- x(s+1) -> B rows 0..127 (from prefetched regs) ----
            {
                uint2 lo, hi = split_pack4(rx0, lo);
                int k0 = tid >> 2, j0 = tid & 3;
                *(uint2*)(smem + B_HI_OFF + k0 * 32 + j0 * 8) = hi;
                *(uint2*)(smem + B_LO_OFF + k0 * 32 + j0 * 8) = lo;
                int i1 = tid + 256;
                int k1 = i1 >> 2, j1 = i1 & 3;
                hi = split_pack4(rx1, lo);
                *(uint2*)(smem + B_HI_OFF + k1 * 32 + j1 * 8) = hi;
                *(uint2*)(smem + B_LO_OFF + k1 * 32 + j1 * 8) = lo;
            }
        }

        // ---- outputs (fire and forget) ----
        const int b_glob = b_base + cb;
        const int h_glob = rs * 32 + hh0;
        *(float2*)(out + ((size_t)b_glob * S_LEN + t) * 512 + dir * 256 + h_glob)
            = make_float2(hv0, hv1);
        if (s == S_LEN - 1) {
            size_t base = (size_t)128 * S_LEN * 512;
            size_t off  = ((size_t)dir * 128 + b_glob) * 256 + h_glob;
            *(float2*)(out + base + off) = make_float2(hv0, hv1);
            *(float2*)(out + base + 2u * 128 * 256 + off) = make_float2(c0, c1);
        }
        __syncthreads();                     // x STS visible before next x-GEMM
    }

    cluster_sync();
}

extern "C" void kernel_launch(void* const* d_in, const int* in_sizes, int n_in,
                              void* d_out, int out_size) {
    const float* x  = (const float*)d_in[0];
    const float* Wf = (const float*)d_in[1];
    const float* bf = (const float*)d_in[2];
    const float* Wb = (const float*)d_in[3];
    const float* bb = (const float*)d_in[4];
    float* out = (float*)d_out;

    cudaFuncSetAttribute(bilstm_mma_kernel,
                         cudaFuncAttributeMaxDynamicSharedMemorySize,
                         SMEM_BYTES);

    bilstm_mma_kernel<<<128, NTHR, SMEM_BYTES>>>(x, Wf, bf, Wb, bb, out);
}

// round 8
// speedup vs baseline: 4.6019x; 4.6019x over previous
#include <cuda_runtime.h>
#include <cuda_bf16.h>
#include <stdint.h>

// BiLSTM B=128,S=1024,D=128,H=256 — bf16 3-split HMMA, gmem slice exchange.
// 128 CTAs = dir(2) x rowslice(8, M=128 = 4 gates x 32 h) x btile(8, N=16).
// Exchange: producer converts its 32x16 h slice to bf16 hi/lo ONCE, STGs 2KB,
// sets a per-producer flag; each consumer warp w polls producer w's flag and
// copies the ldsm-ready slice into its B region. No CTA-wide barrier.

#define S_LEN 1024
#define NTHR  256

#define A_HI_OFF 0          // 8mt x 24kt x 512B
#define A_LO_OFF 98304
#define B_HI_OFF 196608     // [384][16] bf16, 32B rows
#define B_LO_OFF 208896
#define Z_OFF    221184     // float z[128][16]
#define SMEM_BYTES 229376

__device__ unsigned char g_hx[2][2][8][8][2048]; // [parity][dir][btl][rs][hi1K|lo1K]
__device__ unsigned g_flag[128];                 // [dir*64 + btl*8 + rs]

__global__ void reset_flag_kernel() {
    if (threadIdx.x < 128) g_flag[threadIdx.x] = 0u;
}

__device__ __forceinline__ uint32_t smem_u32(const void* p) {
    uint32_t a;
    asm("{ .reg .u64 t; cvta.to.shared.u64 t, %1; cvt.u32.u64 %0, t; }"
        : "=r"(a) : "l"(p));
    return a;
}
__device__ __forceinline__ unsigned ld_acquire_gpu(const unsigned* p) {
    unsigned v;
    asm volatile("ld.acquire.gpu.global.u32 %0, [%1];" : "=r"(v) : "l"(p) : "memory");
    return v;
}
__device__ __forceinline__ void ldsm4(uint32_t* r, uint32_t a) {
    asm volatile("ldmatrix.sync.aligned.m8n8.x4.shared.b16 {%0,%1,%2,%3}, [%4];"
                 : "=r"(r[0]), "=r"(r[1]), "=r"(r[2]), "=r"(r[3]) : "r"(a));
}
__device__ __forceinline__ void ldsm4t(uint32_t* r, uint32_t a) {
    asm volatile("ldmatrix.sync.aligned.m8n8.x4.trans.shared.b16 {%0,%1,%2,%3}, [%4];"
                 : "=r"(r[0]), "=r"(r[1]), "=r"(r[2]), "=r"(r[3]) : "r"(a));
}
__device__ __forceinline__ void mma16816(float* d, const uint32_t* a, const uint32_t* b) {
    asm volatile(
        "mma.sync.aligned.m16n8k16.row.col.f32.bf16.bf16.f32 "
        "{%0,%1,%2,%3}, {%4,%5,%6,%7}, {%8,%9}, {%0,%1,%2,%3};"
        : "+f"(d[0]), "+f"(d[1]), "+f"(d[2]), "+f"(d[3])
        : "r"(a[0]), "r"(a[1]), "r"(a[2]), "r"(a[3]), "r"(b[0]), "r"(b[1]));
}

__device__ __forceinline__ uint2 split_pack4(float4 v, uint2& lo_out) {
    __nv_bfloat16 h0 = __float2bfloat16_rn(v.x), h1 = __float2bfloat16_rn(v.y);
    __nv_bfloat16 h2 = __float2bfloat16_rn(v.z), h3 = __float2bfloat16_rn(v.w);
    __nv_bfloat16 l0 = __float2bfloat16_rn(v.x - __bfloat162float(h0));
    __nv_bfloat16 l1 = __float2bfloat16_rn(v.y - __bfloat162float(h1));
    __nv_bfloat16 l2 = __float2bfloat16_rn(v.z - __bfloat162float(h2));
    __nv_bfloat16 l3 = __float2bfloat16_rn(v.w - __bfloat162float(h3));
    uint2 hi;
    hi.x = ((uint32_t)__bfloat16_as_ushort(h1) << 16) | __bfloat16_as_ushort(h0);
    hi.y = ((uint32_t)__bfloat16_as_ushort(h3) << 16) | __bfloat16_as_ushort(h2);
    lo_out.x = ((uint32_t)__bfloat16_as_ushort(l1) << 16) | __bfloat16_as_ushort(l0);
    lo_out.y = ((uint32_t)__bfloat16_as_ushort(l3) << 16) | __bfloat16_as_ushort(l2);
    return hi;
}
__device__ __forceinline__ float sigmoidf_fast(float x) {
    return 1.0f / (1.0f + __expf(-x));
}
__device__ __forceinline__ float tanhf_fast(float x) {
    return 1.0f - 2.0f / (1.0f + __expf(2.0f * x));
}

__global__ void __launch_bounds__(NTHR, 1)
bilstm_mma_kernel(const float* __restrict__ x,
                  const float* __restrict__ Wf, const float* __restrict__ bf,
                  const float* __restrict__ Wb, const float* __restrict__ bb,
                  float* __restrict__ out)
{
    extern __shared__ char smem[];
    const uint32_t sb = smem_u32(smem);
    const int tid  = threadIdx.x;
    const int wid  = tid >> 5;
    const int lane = tid & 31;

    const int dir = blockIdx.x >> 6;
    const int rs  = (blockIdx.x >> 3) & 7;
    const int btl = blockIdx.x & 7;
    const int b_base = btl * 16;

    const float* W   = dir ? Wb : Wf;        // (4,256,384)
    const float* bia = dir ? bb : bf;
    float* z_s = (float*)(smem + Z_OFF);

    // zero h-region rows 128..383 of both B buffers (s=0 state)
    for (int i = tid; i < 512; i += NTHR) {
        ((uint4*)(smem + B_HI_OFF + 4096))[i] = make_uint4(0, 0, 0, 0);
        ((uint4*)(smem + B_LO_OFF + 4096))[i] = make_uint4(0, 0, 0, 0);
    }

    // ---- A: weights -> bf16 hi/lo ldmatrix tiles ----
    for (int idx = tid; idx < 128 * 96; idx += NTHR) {
        int r = idx / 96, j = idx % 96, k0 = j * 4;
        int wr = (r >> 5) * 256 + rs * 32 + (r & 31);
        float4 v = *(const float4*)(W + (size_t)wr * 384 + k0);
        uint2 lo, hi = split_pack4(v, lo);
        uint32_t byte = (uint32_t)(((r >> 4) * 24 + (k0 >> 4)) * 512
                       + (((k0 >> 3) & 1) * 2 + ((r >> 3) & 1)) * 128
                       + (r & 7) * 16 + (k0 & 7) * 2);
        *(uint2*)(smem + A_HI_OFF + byte) = hi;
        *(uint2*)(smem + A_LO_OFF + byte) = lo;
    }

    const int r1 = wid * 16 + (lane >> 2);
    const int r2 = r1 + 8;
    const float bv1 = bia[(r1 >> 5) * 256 + rs * 32 + (r1 & 31)];
    const float bv2 = bia[(r2 >> 5) * 256 + rs * 32 + (r2 & 31)];

    // x(0) fill into B rows 0..127
    {
        const int t0 = dir ? (S_LEN - 1) : 0;
        for (int i = tid; i < 512; i += NTHR) {
            int k = i >> 2, j = i & 3;
            float4 v = __ldg((const float4*)(x + (size_t)k * (S_LEN * 128)
                                               + (size_t)t0 * 128 + b_base + j * 4));
            uint2 lo, hi = split_pack4(v, lo);
            *(uint2*)(smem + B_HI_OFF + k * 32 + j * 8) = hi;
            *(uint2*)(smem + B_LO_OFF + k * 32 + j * 8) = lo;
        }
    }
    __syncthreads();

    // ldmatrix base addrs
    const uint32_t aHi0 = sb + A_HI_OFF + (uint32_t)(wid * 24 * 512)
                        + ((lane >> 3) * 128) + ((lane & 7) * 16);
    const int sub = lane >> 3;
    const int kk  = (lane & 7) + (sub & 1) * 8;
    const int nb  = sub >> 1;
    const uint32_t bHi0 = sb + B_HI_OFF + (uint32_t)(kk * 32 + nb * 16);

    // gate cells
    const int cb  = tid & 15;
    const int hh0 = (tid >> 4) << 1;
    float c0 = 0.0f, c1 = 0.0f;

    const unsigned* myflag = &g_flag[dir * 64 + btl * 8 + wid];
    const int fidx = dir * 64 + btl * 8 + rs;

    for (int s = 0; s < S_LEN; ++s) {
        const int t = dir ? (S_LEN - 1 - s) : s;

        float a0e[4] = {0,0,0,0}, a0o[4] = {0,0,0,0};
        float a1e[4] = {0,0,0,0}, a1o[4] = {0,0,0,0};
        uint32_t aH = aHi0, bH = bHi0;

        // ---- phase1: x-part GEMM kt 0..7 ----
#pragma unroll
        for (int kt = 0; kt < 8; ++kt) {
            uint32_t ah[4], al[4], bh[4], bl[4];
            ldsm4 (ah, aH);
            ldsm4 (al, aH + 98304u);
            ldsm4t(bh, bH);
            ldsm4t(bl, bH + 12288u);
            float* A0 = (kt & 1) ? a0o : a0e;
            float* A1 = (kt & 1) ? a1o : a1e;
            mma16816(A0, ah, bh);  mma16816(A1, ah, bh + 2);
            mma16816(A0, ah, bl);  mma16816(A1, ah, bl + 2);
            mma16816(A0, al, bh);  mma16816(A1, al, bh + 2);
            aH += 512u; bH += 512u;
        }

        // ---- phase2: per-warp poll + copy slice wid of h(s-1) ----
        if (s > 0) {
            while (ld_acquire_gpu(myflag) < (unsigned)s) {}
            const unsigned char* src = &g_hx[(s - 1) & 1][dir][btl][wid][0];
            uint4 v0 = __ldcg((const uint4*)src + lane);
            uint4 v1 = __ldcg((const uint4*)src + 32 + lane);
            uint4 v2 = __ldcg((const uint4*)src + 64 + lane);
            uint4 v3 = __ldcg((const uint4*)src + 96 + lane);
#pragma unroll
            for (int rr = 0; rr < 4; ++rr) {
                int idx = rr * 512 + lane * 16;
                int buf = idx >> 10, rem = idx & 1023;
                uint4 v = (rr == 0) ? v0 : (rr == 1) ? v1 : (rr == 2) ? v2 : v3;
                *(uint4*)(smem + (buf ? B_LO_OFF : B_HI_OFF) + 4096
                               + wid * 1024 + rem) = v;
            }
        }
        __syncthreads();

        // ---- phase3: h-part GEMM kt 8..23 ----
#pragma unroll
        for (int kt = 0; kt < 16; ++kt) {
            uint32_t ah[4], al[4], bh[4], bl[4];
            ldsm4 (ah, aH);
            ldsm4 (al, aH + 98304u);
            ldsm4t(bh, bH);
            ldsm4t(bl, bH + 12288u);
            float* A0 = (kt & 1) ? a0o : a0e;
            float* A1 = (kt & 1) ? a1o : a1e;
            mma16816(A0, ah, bh);  mma16816(A1, ah, bh + 2);
            mma16816(A0, ah, bl);  mma16816(A1, ah, bl + 2);
            mma16816(A0, al, bh);  mma16816(A1, al, bh + 2);
            aH += 512u; bH += 512u;
        }

        // ---- phase4: stage z (+bias) ----
        const int n0 = (lane & 3) * 2;
        *(float2*)(z_s + r1 * 16 + n0)     = make_float2(a0e[0] + a0o[0] + bv1, a0e[1] + a0o[1] + bv1);
        *(float2*)(z_s + r2 * 16 + n0)     = make_float2(a0e[2] + a0o[2] + bv2, a0e[3] + a0o[3] + bv2);
        *(float2*)(z_s + r1 * 16 + n0 + 8) = make_float2(a1e[0] + a1o[0] + bv1, a1e[1] + a1o[1] + bv1);
        *(float2*)(z_s + r2 * 16 + n0 + 8) = make_float2(a1e[2] + a1o[2] + bv2, a1e[3] + a1o[3] + bv2);
        __syncthreads();

        // ---- phase5: x prefetch, gates, publish ----
        float4 rx0, rx1;
        if (s + 1 < S_LEN) {
            const int tn = dir ? (S_LEN - 2 - s) : (s + 1);
            int k0 = tid >> 2, j0 = tid & 3;
            rx0 = __ldg((const float4*)(x + (size_t)k0 * (S_LEN * 128)
                                          + (size_t)tn * 128 + b_base + j0 * 4));
            int i1 = tid + 256;
            int k1 = i1 >> 2, j1 = i1 & 3;
            rx1 = __ldg((const float4*)(x + (size_t)k1 * (S_LEN * 128)
                                          + (size_t)tn * 128 + b_base + j1 * 4));
        }

        float zf0 = z_s[(0  + hh0) * 16 + cb], zf1 = z_s[(1  + hh0) * 16 + cb];
        float zi0 = z_s[(32 + hh0) * 16 + cb], zi1 = z_s[(33 + hh0) * 16 + cb];
        float zc0 = z_s[(64 + hh0) * 16 + cb], zc1 = z_s[(65 + hh0) * 16 + cb];
        float zo0 = z_s[(96 + hh0) * 16 + cb], zo1 = z_s[(97 + hh0) * 16 + cb];

        c0 = sigmoidf_fast(zf0) * c0 + sigmoidf_fast(zi0) * tanhf_fast(zc0);
        c1 = sigmoidf_fast(zf1) * c1 + sigmoidf_fast(zi1) * tanhf_fast(zc1);
        float hv0 = sigmoidf_fast(zo0) * tanhf_fast(c0);
        float hv1 = sigmoidf_fast(zo1) * tanhf_fast(c1);

        if (s + 1 < S_LEN) {
            // producer slice STG (bf16 hi/lo, ldsm-ready layout)
            unsigned char* dst = &g_hx[s & 1][dir][btl][rs][0];
            __nv_bfloat16 h0 = __float2bfloat16_rn(hv0);
            __nv_bfloat16 h1 = __float2bfloat16_rn(hv1);
            __nv_bfloat16 l0 = __float2bfloat16_rn(hv0 - __bfloat162float(h0));
            __nv_bfloat16 l1 = __float2bfloat16_rn(hv1 - __bfloat162float(h1));
            *(unsigned short*)(dst + hh0 * 32 + cb * 2)              = __bfloat16_as_ushort(h0);
            *(unsigned short*)(dst + (hh0 + 1) * 32 + cb * 2)        = __bfloat16_as_ushort(h1);
            *(unsigned short*)(dst + 1024 + hh0 * 32 + cb * 2)       = __bfloat16_as_ushort(l0);
            *(unsigned short*)(dst + 1024 + (hh0 + 1) * 32 + cb * 2) = __bfloat16_as_ushort(l1);
            __threadfence();
            __syncthreads();
            if (tid == 0)
                *(volatile unsigned*)&g_flag[fidx] = (unsigned)(s + 1);
        }

        // outputs (off the critical path)
        const int b_glob = b_base + cb;
        const int h_glob = rs * 32 + hh0;
        *(float2*)(out + ((size_t)b_glob * S_LEN + t) * 512 + dir * 256 + h_glob)
            = make_float2(hv0, hv1);
        if (s == S_LEN - 1) {
            size_t base = (size_t)128 * S_LEN * 512;
            size_t off  = ((size_t)dir * 128 + b_glob) * 256 + h_glob;
            *(float2*)(out + base + off) = make_float2(hv0, hv1);
            *(float2*)(out + base + 2u * 128 * 256 + off) = make_float2(c0, c1);
        }

        // x(s+1) -> B rows 0..127
        if (s + 1 < S_LEN) {
            uint2 lo, hi = split_pack4(rx0, lo);
            int k0 = tid >> 2, j0 = tid & 3;
            *(uint2*)(smem + B_HI_OFF + k0 * 32 + j0 * 8) = hi;
            *(uint2*)(smem + B_LO_OFF + k0 * 32 + j0 * 8) = lo;
            int i1 = tid + 256;
            int k1 = i1 >> 2, j1 = i1 & 3;
            hi = split_pack4(rx1, lo);
            *(uint2*)(smem + B_HI_OFF + k1 * 32 + j1 * 8) = hi;
            *(uint2*)(smem + B_LO_OFF + k1 * 32 + j1 * 8) = lo;
        }
        __syncthreads();
    }
}

extern "C" void kernel_launch(void* const* d_in, const int* in_sizes, int n_in,
                              void* d_out, int out_size) {
    const float* x  = (const float*)d_in[0];
    const float* Wf = (const float*)d_in[1];
    const float* bf = (const float*)d_in[2];
    const float* Wb = (const float*)d_in[3];
    const float* bb = (const float*)d_in[4];
    float* out = (float*)d_out;

    cudaFuncSetAttribute(bilstm_mma_kernel,
                         cudaFuncAttributeMaxDynamicSharedMemorySize,
                         SMEM_BYTES);

    reset_flag_kernel<<<1, 128>>>();
    bilstm_mma_kernel<<<128, NTHR, SMEM_BYTES>>>(x, Wf, bf, Wb, bb, out);
}

// round 9
// speedup vs baseline: 5.1819x; 1.1260x over previous
#include <cuda_runtime.h>
#include <cuda_bf16.h>
#include <stdint.h>

// BiLSTM B=128,S=1024,D=128,H=256 — bf16 3-split HMMA, gmem slice exchange.
// 128 CTAs = dir(2) x rowslice(8, M=128 = 4gates x 32h) x btile(8, N=16).
// 512 threads: warp pairs (w, w+8) split K (even/odd kt) of strip w&7;
// partials reduced via zE/zO smem buffers (overlaying the B x-region).
// Publish: per-warp red.release arrivals; consumers poll flag >= 16*s.

#define S_LEN 1024
#define NTHR  512

#define A_HI_OFF 0          // 8 strips x 24kt x 512B
#define A_LO_OFF 98304
#define B_HI_OFF 196608     // [384][16] bf16, 32B rows (x rows 0..127, h 128..383)
#define B_LO_OFF 212992
#define ZE_OFF   196608     // overlays B_HI x rows (z stage after x-GEMM)
#define ZO_OFF   212992     // overlays B_LO x rows
#define SMEM_BYTES 229376

__device__ unsigned char g_hx[2][2][8][8][2048]; // [parity][dir][btl][rs][hi1K|lo1K]
__device__ unsigned g_flag[128];                 // cumulative warp arrivals

__global__ void reset_flag_kernel() {
    if (threadIdx.x < 128) g_flag[threadIdx.x] = 0u;
}

__device__ __forceinline__ uint32_t smem_u32(const void* p) {
    uint32_t a;
    asm("{ .reg .u64 t; cvta.to.shared.u64 t, %1; cvt.u32.u64 %0, t; }"
        : "=r"(a) : "l"(p));
    return a;
}
__device__ __forceinline__ unsigned ld_acquire_gpu(const unsigned* p) {
    unsigned v;
    asm volatile("ld.acquire.gpu.global.u32 %0, [%1];" : "=r"(v) : "l"(p) : "memory");
    return v;
}
__device__ __forceinline__ void red_release_gpu(unsigned* p, unsigned v) {
    asm volatile("red.release.gpu.global.add.u32 [%0], %1;" :: "l"(p), "r"(v) : "memory");
}
__device__ __forceinline__ void ldsm4(uint32_t* r, uint32_t a) {
    asm volatile("ldmatrix.sync.aligned.m8n8.x4.shared.b16 {%0,%1,%2,%3}, [%4];"
                 : "=r"(r[0]), "=r"(r[1]), "=r"(r[2]), "=r"(r[3]) : "r"(a));
}
__device__ __forceinline__ void ldsm4t(uint32_t* r, uint32_t a) {
    asm volatile("ldmatrix.sync.aligned.m8n8.x4.trans.shared.b16 {%0,%1,%2,%3}, [%4];"
                 : "=r"(r[0]), "=r"(r[1]), "=r"(r[2]), "=r"(r[3]) : "r"(a));
}
__device__ __forceinline__ void mma16816(float* d, const uint32_t* a, const uint32_t* b) {
    asm volatile(
        "mma.sync.aligned.m16n8k16.row.col.f32.bf16.bf16.f32 "
        "{%0,%1,%2,%3}, {%4,%5,%6,%7}, {%8,%9}, {%0,%1,%2,%3};"
        : "+f"(d[0]), "+f"(d[1]), "+f"(d[2]), "+f"(d[3])
        : "r"(a[0]), "r"(a[1]), "r"(a[2]), "r"(a[3]), "r"(b[0]), "r"(b[1]));
}

__device__ __forceinline__ uint2 split_pack4(float4 v, uint2& lo_out) {
    __nv_bfloat16 h0 = __float2bfloat16_rn(v.x), h1 = __float2bfloat16_rn(v.y);
    __nv_bfloat16 h2 = __float2bfloat16_rn(v.z), h3 = __float2bfloat16_rn(v.w);
    __nv_bfloat16 l0 = __float2bfloat16_rn(v.x - __bfloat162float(h0));
    __nv_bfloat16 l1 = __float2bfloat16_rn(v.y - __bfloat162float(h1));
    __nv_bfloat16 l2 = __float2bfloat16_rn(v.z - __bfloat162float(h2));
    __nv_bfloat16 l3 = __float2bfloat16_rn(v.w - __bfloat162float(h3));
    uint2 hi;
    hi.x = ((uint32_t)__bfloat16_as_ushort(h1) << 16) | __bfloat16_as_ushort(h0);
    hi.y = ((uint32_t)__bfloat16_as_ushort(h3) << 16) | __bfloat16_as_ushort(h2);
    lo_out.x = ((uint32_t)__bfloat16_as_ushort(l1) << 16) | __bfloat16_as_ushort(l0);
    lo_out.y = ((uint32_t)__bfloat16_as_ushort(l3) << 16) | __bfloat16_as_ushort(l2);
    return hi;
}
__device__ __forceinline__ float sigmoidf_fast(float x) {
    return 1.0f / (1.0f + __expf(-x));
}
__device__ __forceinline__ float tanhf_fast(float x) {
    return 1.0f - 2.0f / (1.0f + __expf(2.0f * x));
}

__global__ void __launch_bounds__(NTHR, 1)
bilstm_mma_kernel(const float* __restrict__ x,
                  const float* __restrict__ Wf, const float* __restrict__ bf,
                  const float* __restrict__ Wb, const float* __restrict__ bb,
                  float* __restrict__ out)
{
    extern __shared__ char smem[];
    const uint32_t sb = smem_u32(smem);
    const int tid  = threadIdx.x;
    const int wid  = tid >> 5;           // 0..15
    const int lane = tid & 31;
    const int wlow  = wid & 7;           // strip
    const int whalf = wid >> 3;          // 0=even kt, 1=odd kt

    const int dir = blockIdx.x >> 6;
    const int rs  = (blockIdx.x >> 3) & 7;
    const int btl = blockIdx.x & 7;
    const int b_base = btl * 16;

    const float* W   = dir ? Wb : Wf;    // (4,256,384)
    const float* bia = dir ? bb : bf;

    // zero h-region rows 128..383 of both B buffers (s=0 state)
    for (int i = tid; i < 1024; i += NTHR) {
        int buf = i >> 9, r = i & 511;
        ((uint4*)(smem + (buf ? B_LO_OFF : B_HI_OFF) + 4096))[r] = make_uint4(0, 0, 0, 0);
    }

    // ---- A: weights -> bf16 hi/lo ldmatrix tiles ----
    for (int idx = tid; idx < 128 * 96; idx += NTHR) {
        int r = idx / 96, j = idx % 96, k0 = j * 4;
        int wr = (r >> 5) * 256 + rs * 32 + (r & 31);
        float4 v = *(const float4*)(W + (size_t)wr * 384 + k0);
        uint2 lo, hi = split_pack4(v, lo);
        uint32_t byte = (uint32_t)(((r >> 4) * 24 + (k0 >> 4)) * 512
                       + (((k0 >> 3) & 1) * 2 + ((r >> 3) & 1)) * 128
                       + (r & 7) * 16 + (k0 & 7) * 2);
        *(uint2*)(smem + A_HI_OFF + byte) = hi;
        *(uint2*)(smem + A_LO_OFF + byte) = lo;
    }

    // gate-cell mapping: 1 cell per thread
    const int cb = tid & 15;             // batch 0..15
    const int hh = tid >> 4;             // h 0..31 within strip
    const float bF = bia[0 * 256 + rs * 32 + hh];
    const float bI = bia[1 * 256 + rs * 32 + hh];
    const float bC = bia[2 * 256 + rs * 32 + hh];
    const float bO = bia[3 * 256 + rs * 32 + hh];
    float cstate = 0.0f;

    // x(0) fill into B rows 0..127 (1 float4 per thread)
    {
        const int t0 = dir ? (S_LEN - 1) : 0;
        int k = tid >> 2, j = tid & 3;
        float4 v = __ldg((const float4*)(x + (size_t)k * (S_LEN * 128)
                                           + (size_t)t0 * 128 + b_base + j * 4));
        uint2 lo, hi = split_pack4(v, lo);
        *(uint2*)(smem + B_HI_OFF + k * 32 + j * 8) = hi;
        *(uint2*)(smem + B_LO_OFF + k * 32 + j * 8) = lo;
    }
    __syncthreads();

    // ldmatrix base addrs
    const uint32_t aBase = sb + A_HI_OFF + (uint32_t)(wlow * 24 * 512)
                         + ((lane >> 3) * 128) + ((lane & 7) * 16);
    const int sub = lane >> 3;
    const int kkl = (lane & 7) + (sub & 1) * 8;
    const int nb  = sub >> 1;
    const uint32_t bBase = sb + B_HI_OFF + (uint32_t)(kkl * 32 + nb * 16);

    // z-staging rows for this warp's strip
    const int r1 = wlow * 16 + (lane >> 2);
    const int r2 = r1 + 8;
    const int n0 = (lane & 3) * 2;
    float* zmine = (float*)(smem + (whalf ? ZO_OFF : ZE_OFF));
    const float* zE = (const float*)(smem + ZE_OFF);
    const float* zO = (const float*)(smem + ZO_OFF);

    const unsigned* myflag = &g_flag[dir * 64 + btl * 8 + wlow];
    const int fidx = dir * 64 + btl * 8 + rs;

    for (int s = 0; s < S_LEN; ++s) {
        const int t = dir ? (S_LEN - 1 - s) : s;

        float a0e[4] = {0,0,0,0}, a0o[4] = {0,0,0,0};
        float a1e[4] = {0,0,0,0}, a1o[4] = {0,0,0,0};

        // ---- phase1: x-part GEMM, 4 kts (kt = whalf, whalf+2, ...) ----
        {
            int kt = whalf;
#pragma unroll
            for (int i = 0; i < 4; ++i, kt += 2) {
                uint32_t aH = aBase + (uint32_t)kt * 512u;
                uint32_t bH = bBase + (uint32_t)kt * 512u;
                uint32_t ah[4], al[4], bh[4], bl[4];
                ldsm4 (ah, aH);
                ldsm4 (al, aH + 98304u);
                ldsm4t(bh, bH);
                ldsm4t(bl, bH + 16384u);
                float* A0 = (i & 1) ? a0o : a0e;
                float* A1 = (i & 1) ? a1o : a1e;
                mma16816(A0, ah, bh);  mma16816(A1, ah, bh + 2);
                mma16816(A0, ah, bl);  mma16816(A1, ah, bl + 2);
                mma16816(A0, al, bh);  mma16816(A1, al, bh + 2);
            }
        }

        // ---- phase2: poll + copy slice (warp pair w, w+8 -> hi/lo halves) ----
        if (s > 0) {
            unsigned tgt = 16u * (unsigned)s;
            while (ld_acquire_gpu(myflag) < tgt) {}
            const unsigned char* src = &g_hx[(s - 1) & 1][dir][btl][wlow][0]
                                     + whalf * 1024;
            uint4 v0 = __ldcg((const uint4*)(src) + lane);
            uint4 v1 = __ldcg((const uint4*)(src + 512) + lane);
            char* dst = smem + (whalf ? B_LO_OFF : B_HI_OFF) + 4096 + wlow * 1024;
            *((uint4*)dst + lane)      = v0;
            *((uint4*)(dst + 512) + lane) = v1;
        }
        __syncthreads();

        // ---- phase3: h-part GEMM, 8 kts ----
        {
            int kt = 8 + whalf;
#pragma unroll
            for (int i = 0; i < 8; ++i, kt += 2) {
                uint32_t aH = aBase + (uint32_t)kt * 512u;
                uint32_t bH = bBase + (uint32_t)kt * 512u;
                uint32_t ah[4], al[4], bh[4], bl[4];
                ldsm4 (ah, aH);
                ldsm4 (al, aH + 98304u);
                ldsm4t(bh, bH);
                ldsm4t(bl, bH + 16384u);
                float* A0 = (i & 1) ? a0o : a0e;
                float* A1 = (i & 1) ? a1o : a1e;
                mma16816(A0, ah, bh);  mma16816(A1, ah, bh + 2);
                mma16816(A0, ah, bl);  mma16816(A1, ah, bl + 2);
                mma16816(A0, al, bh);  mma16816(A1, al, bh + 2);
            }
        }

        // ---- phase4: stage partial z into zE/zO (overlay of B x rows) ----
        *(float2*)(zmine + r1 * 16 + n0)     = make_float2(a0e[0] + a0o[0], a0e[1] + a0o[1]);
        *(float2*)(zmine + r2 * 16 + n0)     = make_float2(a0e[2] + a0o[2], a0e[3] + a0o[3]);
        *(float2*)(zmine + r1 * 16 + n0 + 8) = make_float2(a1e[0] + a1o[0], a1e[1] + a1o[1]);
        *(float2*)(zmine + r2 * 16 + n0 + 8) = make_float2(a1e[2] + a1o[2], a1e[3] + a1o[3]);
        __syncthreads();

        // ---- phase5: x(s+1) prefetch (regs), gates, publish ----
        float4 rx;
        if (s + 1 < S_LEN) {
            const int tn = dir ? (S_LEN - 2 - s) : (s + 1);
            int k = tid >> 2, j = tid & 3;
            rx = __ldg((const float4*)(x + (size_t)k * (S_LEN * 128)
                                         + (size_t)tn * 128 + b_base + j * 4));
        }

        float zf = zE[(0  + hh) * 16 + cb] + zO[(0  + hh) * 16 + cb] + bF;
        float zi = zE[(32 + hh) * 16 + cb] + zO[(32 + hh) * 16 + cb] + bI;
        float zc = zE[(64 + hh) * 16 + cb] + zO[(64 + hh) * 16 + cb] + bC;
        float zo = zE[(96 + hh) * 16 + cb] + zO[(96 + hh) * 16 + cb] + bO;

        cstate = sigmoidf_fast(zf) * cstate + sigmoidf_fast(zi) * tanhf_fast(zc);
        float hv = sigmoidf_fast(zo) * tanhf_fast(cstate);

        if (s + 1 < S_LEN) {
            unsigned char* dst = &g_hx[s & 1][dir][btl][rs][0];
            __nv_bfloat16 h0 = __float2bfloat16_rn(hv);
            __nv_bfloat16 l0 = __float2bfloat16_rn(hv - __bfloat162float(h0));
            *(unsigned short*)(dst + hh * 32 + cb * 2)        = __bfloat16_as_ushort(h0);
            *(unsigned short*)(dst + 1024 + hh * 32 + cb * 2) = __bfloat16_as_ushort(l0);
            __syncwarp();
            if (lane == 0) red_release_gpu(&g_flag[fidx], 1u);
        }

        // outputs (off critical path)
        const int b_glob = b_base + cb;
        const int h_glob = rs * 32 + hh;
        out[((size_t)b_glob * S_LEN + t) * 512 + dir * 256 + h_glob] = hv;
        if (s == S_LEN - 1) {
            size_t base = (size_t)128 * S_LEN * 512;
            size_t off  = ((size_t)dir * 128 + b_glob) * 256 + h_glob;
            out[base + off] = hv;
            out[base + 2u * 128 * 256 + off] = cstate;
        }
        __syncthreads();   // gates done reading zE/zO

        // ---- phase6: x(s+1) -> B x rows (overwrites z overlay) ----
        if (s + 1 < S_LEN) {
            uint2 lo, hi = split_pack4(rx, lo);
            int k = tid >> 2, j = tid & 3;
            *(uint2*)(smem + B_HI_OFF + k * 32 + j * 8) = hi;
            *(uint2*)(smem + B_LO_OFF + k * 32 + j * 8) = lo;
        }
        __syncthreads();
    }
}

extern "C" void kernel_launch(void* const* d_in, const int* in_sizes, int n_in,
                              void* d_out, int out_size) {
    const float* x  = (const float*)d_in[0];
    const float* Wf = (const float*)d_in[1];
    const float* bf = (const float*)d_in[2];
    const float* Wb = (const float*)d_in[3];
    const float* bb = (const float*)d_in[4];
    float* out = (float*)d_out;

    cudaFuncSetAttribute(bilstm_mma_kernel,
                         cudaFuncAttributeMaxDynamicSharedMemorySize,
                         SMEM_BYTES);

    reset_flag_kernel<<<1, 128>>>();
    bilstm_mma_kernel<<<128, NTHR, SMEM_BYTES>>>(x, Wf, bf, Wb, bb, out);
}

// round 11
// speedup vs baseline: 5.2410x; 1.0114x over previous
#include <cuda_runtime.h>
#include <cuda_bf16.h>
#include <stdint.h>

// BiLSTM B=128,S=1024,D=128,H=256 — bf16 3-split HMMA, gmem slice exchange.
// 128 CTAs = dir(2) x rowslice(8, M=128) x btile(8, N=16). 512 threads:
// warp pairs (w, w+8) split K. B stored in ldsm-native 128B tiles
// (tile = (k>>3)*2 + (n>>3)) -> conflict-free ldmatrix. z reduced via one
// 8KB buffer (odd STS, even add). 3 __syncthreads per step.

#define S_LEN 1024
#define NTHR  512

#define A_HI_OFF 0          // 8 strips x 24kt x 512B
#define A_LO_OFF 98304
#define B_HI_OFF 196608     // 48 tiles x 128B x (x 4KB | h 8KB)
#define B_LO_OFF 208896
#define Z_OFF    221184     // float z[128][16] = 8KB
#define SMEM_BYTES 229376

__device__ unsigned char g_hx[2][2][8][8][2048]; // [parity][dir][btl][rs][hi1K|lo1K]
__device__ unsigned g_flag[128];                 // cumulative warp arrivals

__global__ void reset_flag_kernel() {
    if (threadIdx.x < 128) g_flag[threadIdx.x] = 0u;
}

__device__ __forceinline__ uint32_t smem_u32(const void* p) {
    uint32_t a;
    asm("{ .reg .u64 t; cvta.to.shared.u64 t, %1; cvt.u32.u64 %0, t; }"
        : "=r"(a) : "l"(p));
    return a;
}
__device__ __forceinline__ unsigned ld_acquire_gpu(const unsigned* p) {
    unsigned v;
    asm volatile("ld.acquire.gpu.global.u32 %0, [%1];" : "=r"(v) : "l"(p) : "memory");
    return v;
}
__device__ __forceinline__ void red_release_gpu(unsigned* p, unsigned v) {
    asm volatile("red.release.gpu.global.add.u32 [%0], %1;" :: "l"(p), "r"(v) : "memory");
}
__device__ __forceinline__ void ldsm4(uint32_t* r, uint32_t a) {
    asm volatile("ldmatrix.sync.aligned.m8n8.x4.shared.b16 {%0,%1,%2,%3}, [%4];"
                 : "=r"(r[0]), "=r"(r[1]), "=r"(r[2]), "=r"(r[3]) : "r"(a));
}
__device__ __forceinline__ void ldsm4t(uint32_t* r, uint32_t a) {
    asm volatile("ldmatrix.sync.aligned.m8n8.x4.trans.shared.b16 {%0,%1,%2,%3}, [%4];"
                 : "=r"(r[0]), "=r"(r[1]), "=r"(r[2]), "=r"(r[3]) : "r"(a));
}
__device__ __forceinline__ void mma16816(float* d, const uint32_t* a, const uint32_t* b) {
    asm volatile(
        "mma.sync.aligned.m16n8k16.row.col.f32.bf16.bf16.f32 "
        "{%0,%1,%2,%3}, {%4,%5,%6,%7}, {%8,%9}, {%0,%1,%2,%3};"
        : "+f"(d[0]), "+f"(d[1]), "+f"(d[2]), "+f"(d[3])
        : "r"(a[0]), "r"(a[1]), "r"(a[2]), "r"(a[3]), "r"(b[0]), "r"(b[1]));
}

__device__ __forceinline__ uint2 split_pack4(float4 v, uint2& lo_out) {
    __nv_bfloat16 h0 = __float2bfloat16_rn(v.x), h1 = __float2bfloat16_rn(v.y);
    __nv_bfloat16 h2 = __float2bfloat16_rn(v.z), h3 = __float2bfloat16_rn(v.w);
    __nv_bfloat16 l0 = __float2bfloat16_rn(v.x - __bfloat162float(h0));
    __nv_bfloat16 l1 = __float2bfloat16_rn(v.y - __bfloat162float(h1));
    __nv_bfloat16 l2 = __float2bfloat16_rn(v.z - __bfloat162float(h2));
    __nv_bfloat16 l3 = __float2bfloat16_rn(v.w - __bfloat162float(h3));
    uint2 hi;
    hi.x = ((uint32_t)__bfloat16_as_ushort(h1) << 16) | __bfloat16_as_ushort(h0);
    hi.y = ((uint32_t)__bfloat16_as_ushort(h3) << 16) | __bfloat16_as_ushort(h2);
    lo_out.x = ((uint32_t)__bfloat16_as_ushort(l1) << 16) | __bfloat16_as_ushort(l0);
    lo_out.y = ((uint32_t)__bfloat16_as_ushort(l3) << 16) | __bfloat16_as_ushort(l2);
    return hi;
}
__device__ __forceinline__ float sigmoidf_fast(float x) {
    return 1.0f / (1.0f + __expf(-x));
}
__device__ __forceinline__ float tanhf_fast(float x) {
    return 1.0f - 2.0f / (1.0f + __expf(2.0f * x));
}

__global__ void __launch_bounds__(NTHR, 1)
bilstm_mma_kernel(const float* __restrict__ x,
                  const float* __restrict__ Wf, const float* __restrict__ bf,
                  const float* __restrict__ Wb, const float* __restrict__ bb,
                  float* __restrict__ out)
{
    extern __shared__ char smem[];
    const uint32_t sb = smem_u32(smem);
    const int tid  = threadIdx.x;
    const int wid  = tid >> 5;           // 0..15
    const int lane = tid & 31;
    const int wlow  = wid & 7;           // strip
    const int whalf = wid >> 3;          // 0=even kt, 1=odd kt

    const int dir = blockIdx.x >> 6;
    const int rs  = (blockIdx.x >> 3) & 7;
    const int btl = blockIdx.x & 7;
    const int b_base = btl * 16;

    const float* W   = dir ? Wb : Wf;    // (4,256,384)
    const float* bia = dir ? bb : bf;
    float* z_s = (float*)(smem + Z_OFF);

    // zero h-region tiles (s=0 state): bytes 4096..12288 of both buffers
    for (int i = tid; i < 1024; i += NTHR) {
        int buf = i >> 9, r = i & 511;
        ((uint4*)(smem + (buf ? B_LO_OFF : B_HI_OFF) + 4096))[r] = make_uint4(0, 0, 0, 0);
    }

    // ---- A: weights -> bf16 hi/lo ldmatrix tiles ----
    for (int idx = tid; idx < 128 * 96; idx += NTHR) {
        int r = idx / 96, j = idx % 96, k0 = j * 4;
        int wr = (r >> 5) * 256 + rs * 32 + (r & 31);
        float4 v = *(const float4*)(W + (size_t)wr * 384 + k0);
        uint2 lo, hi = split_pack4(v, lo);
        uint32_t byte = (uint32_t)(((r >> 4) * 24 + (k0 >> 4)) * 512
                       + (((k0 >> 3) & 1) * 2 + ((r >> 3) & 1)) * 128
                       + (r & 7) * 16 + (k0 & 7) * 2);
        *(uint2*)(smem + A_HI_OFF + byte) = hi;
        *(uint2*)(smem + A_LO_OFF + byte) = lo;
    }

    // gate-cell mapping: 1 cell per thread
    const int cb = tid & 15;             // batch 0..15
    const int hh = tid >> 4;             // h 0..31 within strip
    const float bF = bia[0 * 256 + rs * 32 + hh];
    const float bI = bia[1 * 256 + rs * 32 + hh];
    const float bC = bia[2 * 256 + rs * 32 + hh];
    const float bO = bia[3 * 256 + rs * 32 + hh];
    float cstate = 0.0f;

    // producer STG offset in tile-native slice layout
    const uint32_t pub_off = (uint32_t)(((hh >> 3) * 2 + (cb >> 3)) * 128
                           + (hh & 7) * 16 + (cb & 7) * 2);

    // x fill helper offsets (tile-native)
    const int xk = tid >> 2, xj = tid & 3;
    const uint32_t xfill_off = (uint32_t)(((xk >> 3) * 2 + (xj >> 1)) * 128
                             + (xk & 7) * 16 + (xj & 1) * 8);

    // x(0) fill
    {
        const int t0 = dir ? (S_LEN - 1) : 0;
        float4 v = __ldg((const float4*)(x + (size_t)xk * (S_LEN * 128)
                                           + (size_t)t0 * 128 + b_base + xj * 4));
        uint2 lo, hi = split_pack4(v, lo);
        *(uint2*)(smem + B_HI_OFF + xfill_off) = hi;
        *(uint2*)(smem + B_LO_OFF + xfill_off) = lo;
    }
    __syncthreads();

    // ldmatrix base addrs
    const uint32_t aBase = sb + A_HI_OFF + (uint32_t)(wlow * 24 * 512)
                         + ((lane >> 3) * 128) + ((lane & 7) * 16);
    const int sub = lane >> 3;
    const uint32_t bBase = sb + B_HI_OFF
                         + (uint32_t)((((sub & 1) * 2) + (sub >> 1)) * 128)
                         + ((lane & 7) * 16);

    // z rows for this warp's strip
    const int r1 = wlow * 16 + (lane >> 2);
    const int r2 = r1 + 8;
    const int n0 = (lane & 3) * 2;

    const unsigned* myflag = &g_flag[dir * 64 + btl * 8 + wlow];
    const int fidx = dir * 64 + btl * 8 + rs;

    for (int s = 0; s < S_LEN; ++s) {
        const int t = dir ? (S_LEN - 1 - s) : s;

        float a0e[4] = {0,0,0,0}, a0o[4] = {0,0,0,0};
        float a1e[4] = {0,0,0,0}, a1o[4] = {0,0,0,0};

        // ---- p1: x-part GEMM, 4 kts ----
        {
            int kt = whalf;
#pragma unroll
            for (int i = 0; i < 4; ++i, kt += 2) {
                uint32_t aH = aBase + (uint32_t)kt * 512u;
                uint32_t bH = bBase + (uint32_t)kt * 512u;
                uint32_t ah[4], al[4], bh[4], bl[4];
                ldsm4 (ah, aH);
                ldsm4 (al, aH + 98304u);
                ldsm4t(bh, bH);
                ldsm4t(bl, bH + 12288u);
                float* A0 = (i & 1) ? a0o : a0e;
                float* A1 = (i & 1) ? a1o : a1e;
                mma16816(A0, ah, bh);  mma16816(A1, ah, bh + 2);
                mma16816(A0, ah, bl);  mma16816(A1, ah, bl + 2);
                mma16816(A0, al, bh);  mma16816(A1, al, bh + 2);
            }
        }

        // ---- p2: poll + copy slice (warp pair -> hi/lo halves, verbatim) ----
        if (s > 0) {
            unsigned tgt = 16u * (unsigned)s;
            while (ld_acquire_gpu(myflag) < tgt) {}
            const unsigned char* src = &g_hx[(s - 1) & 1][dir][btl][wlow][0]
                                     + whalf * 1024;
            uint4 v0 = __ldcg((const uint4*)(src) + lane);
            uint4 v1 = __ldcg((const uint4*)(src + 512) + lane);
            char* dst = smem + (whalf ? B_LO_OFF : B_HI_OFF) + 4096 + wlow * 1024;
            *((uint4*)dst + lane)         = v0;
            *((uint4*)(dst + 512) + lane) = v1;
        }
        __syncthreads();   // syncA

        // x(s+1) prefetch issued early (consumed at p4)
        float4 rx;
        if (s + 1 < S_LEN) {
            const int tn = dir ? (S_LEN - 2 - s) : (s + 1);
            rx = __ldg((const float4*)(x + (size_t)xk * (S_LEN * 128)
                                         + (size_t)tn * 128 + b_base + xj * 4));
        }

        // ---- p3: h-part GEMM, 8 kts ----
        {
            int kt = 8 + whalf;
#pragma unroll
            for (int i = 0; i < 8; ++i, kt += 2) {
                uint32_t aH = aBase + (uint32_t)kt * 512u;
                uint32_t bH = bBase + (uint32_t)kt * 512u;
                uint32_t ah[4], al[4], bh[4], bl[4];
                ldsm4 (ah, aH);
                ldsm4 (al, aH + 98304u);
                ldsm4t(bh, bH);
                ldsm4t(bl, bH + 12288u);
                float* A0 = (i & 1) ? a0o : a0e;
                float* A1 = (i & 1) ? a1o : a1e;
                mma16816(A0, ah, bh);  mma16816(A1, ah, bh + 2);
                mma16816(A0, ah, bl);  mma16816(A1, ah, bl + 2);
                mma16816(A0, al, bh);  mma16816(A1, al, bh + 2);
            }
        }

        // ---- p4: x STS + odd-half z partial STS ----
        if (s + 1 < S_LEN) {
            uint2 lo, hi = split_pack4(rx, lo);
            *(uint2*)(smem + B_HI_OFF + xfill_off) = hi;
            *(uint2*)(smem + B_LO_OFF + xfill_off) = lo;
        }
        if (whalf) {
            *(float2*)(z_s + r1 * 16 + n0)     = make_float2(a0e[0] + a0o[0], a0e[1] + a0o[1]);
            *(float2*)(z_s + r2 * 16 + n0)     = make_float2(a0e[2] + a0o[2], a0e[3] + a0o[3]);
            *(float2*)(z_s + r1 * 16 + n0 + 8) = make_float2(a1e[0] + a1o[0], a1e[1] + a1o[1]);
            *(float2*)(z_s + r2 * 16 + n0 + 8) = make_float2(a1e[2] + a1o[2], a1e[3] + a1o[3]);
        }
        __syncthreads();   // syncB

        // ---- p5: even-half z finalize (LDS + add + STS) ----
        if (!whalf) {
            float2 p0 = *(float2*)(z_s + r1 * 16 + n0);
            float2 p1 = *(float2*)(z_s + r2 * 16 + n0);
            float2 p2 = *(float2*)(z_s + r1 * 16 + n0 + 8);
            float2 p3 = *(float2*)(z_s + r2 * 16 + n0 + 8);
            *(float2*)(z_s + r1 * 16 + n0)     = make_float2(p0.x + a0e[0] + a0o[0], p0.y + a0e[1] + a0o[1]);
            *(float2*)(z_s + r2 * 16 + n0)     = make_float2(p1.x + a0e[2] + a0o[2], p1.y + a0e[3] + a0o[3]);
            *(float2*)(z_s + r1 * 16 + n0 + 8) = make_float2(p2.x + a1e[0] + a1o[0], p2.y + a1e[1] + a1o[1]);
            *(float2*)(z_s + r2 * 16 + n0 + 8) = make_float2(p3.x + a1e[2] + a1o[2], p3.y + a1e[3] + a1o[3]);
        }
        __syncthreads();   // syncC

        // ---- p6: gates, publish, outputs ----
        float zf = z_s[(0  + hh) * 16 + cb] + bF;
        float zi = z_s[(32 + hh) * 16 + cb] + bI;
        float zc = z_s[(64 + hh) * 16 + cb] + bC;
        float zo = z_s[(96 + hh) * 16 + cb] + bO;

        cstate = sigmoidf_fast(zf) * cstate + sigmoidf_fast(zi) * tanhf_fast(zc);
        float hv = sigmoidf_fast(zo) * tanhf_fast(cstate);

        if (s + 1 < S_LEN) {
            unsigned char* dst = &g_hx[s & 1][dir][btl][rs][0];
            __nv_bfloat16 h0 = __float2bfloat16_rn(hv);
            __nv_bfloat16 l0 = __float2bfloat16_rn(hv - __bfloat162float(h0));
            *(unsigned short*)(dst + pub_off)        = __bfloat16_as_ushort(h0);
            *(unsigned short*)(dst + 1024 + pub_off) = __bfloat16_as_ushort(l0);
            __syncwarp();
            if (lane == 0) red_release_gpu(&g_flag[fidx], 1u);
        }

        const int b_glob = b_base + cb;
        const int h_glob = rs * 32 + hh;
        out[((size_t)b_glob * S_LEN + t) * 512 + dir * 256 + h_glob] = hv;
        if (s == S_LEN - 1) {
            size_t base = (size_t)128 * S_LEN * 512;
            size_t off  = ((size_t)dir * 128 + b_glob) * 256 + h_glob;
            out[base + off] = hv;
            out[base + 2u * 128 * 256 + off] = cstate;
        }
        // no end sync needed: syncA of next iter orders z reuse;
        // p1 reads x tiles written at p4 (ordered by syncB).
    }
}

extern "C" void kernel_launch(void* const* d_in, const int* in_sizes, int n_in,
                              void* d_out, int out_size) {
    const float* x  = (const float*)d_in[0];
    const float* Wf = (const float*)d_in[1];
    const float* bf = (const float*)d_in[2];
    const float* Wb = (const float*)d_in[3];
    const float* bb = (const float*)d_in[4];
    float* out = (float*)d_out;

    cudaFuncSetAttribute(bilstm_mma_kernel,
                         cudaFuncAttributeMaxDynamicSharedMemorySize,
                         SMEM_BYTES);

    reset_flag_kernel<<<1, 128>>>();
    bilstm_mma_kernel<<<128, NTHR, SMEM_BYTES>>>(x, Wf, bf, Wb, bb, out);
}